// round 12
// baseline (speedup 1.0000x reference)
#include <cuda_runtime.h>
#include <cuda_fp16.h>
#include <cstdint>

// loss = mean(relu(||(a-p)W||^2 - ||(a-n)W||^2 + 0.2))   (bias b cancels)

#define ALPHA_C   0.2f
#define BTOT      8192
#define KDIM      2304
#define NDIM      128
#define ROWS_CTA  64
#define KC        64
#define KP        72          // diff row pitch (halves): conflict-free ldmatrix
#define WP        136         // W row pitch (halves): conflict-free ldmatrix.trans
#define NCHUNK    (KDIM / KC)       // 36
#define NCTA      (BTOT / ROWS_CTA) // 128

#define DIFF_HALVES (128 * KP)      // 9216  (18432 B)
#define W_HALVES    (KC * WP)       // 8704  (17408 B per buffer)
#define DYN_SMEM_BYTES ((DIFF_HALVES + 2 * W_HALVES) * 2)   // 53248

__device__ __half   g_Wh[KDIM * NDIM];   // W fp16, native [k][n]
__device__ float    g_partial[NCTA];
__device__ unsigned g_ticket = 0;

static __device__ __forceinline__ uint32_t h2u(__half2 h) {
    return *reinterpret_cast<uint32_t*>(&h);
}

// ---------------------------------------------------------------------------
__global__ void convW_kernel(const float* __restrict__ W) {
    int gid = blockIdx.x * blockDim.x + threadIdx.x;     // one float4 each
    float4 v = ((const float4*)W)[gid];
    __half2* out = (__half2*)g_Wh;
    out[gid * 2]     = __floats2half2_rn(v.x, v.y);
    out[gid * 2 + 1] = __floats2half2_rn(v.z, v.w);
}

// ---------------------------------------------------------------------------
#define LDSM4(r0, r1, r2, r3, addr)                                          \
    asm volatile("ldmatrix.sync.aligned.m8n8.x4.shared.b16 {%0,%1,%2,%3}, [%4];" \
                 : "=r"(r0), "=r"(r1), "=r"(r2), "=r"(r3) : "r"(addr))

#define LDSM4T(r0, r1, r2, r3, addr)                                         \
    asm volatile("ldmatrix.sync.aligned.m8n8.x4.trans.shared.b16 {%0,%1,%2,%3}, [%4];" \
                 : "=r"(r0), "=r"(r1), "=r"(r2), "=r"(r3) : "r"(addr))

#define MMA16816(c, a0, a1, a2, a3, b0, b1)                                  \
    asm volatile("mma.sync.aligned.m16n8k16.row.col.f32.f16.f16.f32 "        \
                 "{%0,%1,%2,%3}, {%4,%5,%6,%7}, {%8,%9}, {%0,%1,%2,%3};"     \
                 : "+f"(c[0]), "+f"(c[1]), "+f"(c[2]), "+f"(c[3])            \
                 : "r"(a0), "r"(a1), "r"(a2), "r"(a3), "r"(b0), "r"(b1))

// Streaming LDG.128 — asm volatile pins issue position in the instr stream.
#define LDG_CS128(v, ptr)                                                    \
    asm volatile("ld.global.cs.v4.f32 {%0,%1,%2,%3}, [%4];"                  \
                 : "=f"((v).x), "=f"((v).y), "=f"((v).z), "=f"((v).w)        \
                 : "l"(ptr))

#define CP_ASYNC16(dst_u32, src_ptr)                                         \
    asm volatile("cp.async.cg.shared.global [%0], [%1], 16;"                 \
                 :: "r"(dst_u32), "l"(src_ptr))
#define CP_COMMIT()  asm volatile("cp.async.commit_group;")
#define CP_WAIT1()   asm volatile("cp.async.wait_group 1;")

__global__ void __launch_bounds__(256, 1)
triplet_main_kernel(const float* __restrict__ A,
                    const float* __restrict__ P,
                    const float* __restrict__ Ng,
                    float* __restrict__ out) {
    extern __shared__ __align__(16) __half smem[];
    __half* sdiff = smem;                          // 128 x KP (dp rows 0-63, dn 64-127)
    __half* wbuf0 = smem + DIFF_HALVES;
    __half* wbuf1 = wbuf0 + W_HALVES;
    __shared__ float sD[128][2];
    __shared__ float sRed[4];
    __shared__ int   sIsLast;

    const int tid  = threadIdx.x;
    const int warp = tid >> 5;
    const int lane = tid & 31;
    const int row0 = blockIdx.x * ROWS_CTA;

    const int mq = warp & 3;       // 32-row slice of the merged 128-row tile
    const int nh = warp >> 2;      // 64-col half

    const uint32_t a_base  = (uint32_t)__cvta_generic_to_shared(sdiff);
    const uint32_t w_base[2] = { (uint32_t)__cvta_generic_to_shared(wbuf0),
                                 (uint32_t)__cvta_generic_to_shared(wbuf1) };

    // one-chunk register staging for A/P/N
    float4 ra[4], rp[4], rn[4];

    float acc[2][8][4];
#pragma unroll
    for (int mt = 0; mt < 2; mt++)
#pragma unroll
        for (int j = 0; j < 8; j++)
#pragma unroll
            for (int c = 0; c < 4; c++) acc[mt][j][c] = 0.f;

    // ldmatrix per-lane address components
    const int a_row  = mq * 32 + (lane & 15);
    const int a_kadd = (lane >> 4) * 8;
    const int b_krow = (lane & 7) + ((lane >> 3) & 1) * 8;
    const int b_ncol = nh * 64 + (lane >> 4) * 8;

    // load half-burst h (it = 2h, 2h+1) of chunk at k0 — LDGs pinned in place
    auto loadHalf = [&](int k0, int h) {
#pragma unroll
        for (int it = 2 * h; it < 2 * h + 2; it++) {
            int idx = it * 256 + tid;
            int r = idx >> 4, c4 = idx & 15;           // 16 float4 per 64-float row
            long off = (long)(row0 + r) * KDIM + k0 + c4 * 4;
            LDG_CS128(ra[it], A + off);
            LDG_CS128(rp[it], P + off);
            LDG_CS128(rn[it], Ng + off);
        }
    };

    auto cpasyncW = [&](int k0, uint32_t wb) {
        // 64 k-rows x 128 halves = 1024 x 16B units; 4 per thread
#pragma unroll
        for (int it = 0; it < 4; it++) {
            int g = it * 256 + tid;
            int k = g >> 4, u = g & 15;
            uint32_t dst = wb + (uint32_t)((k * WP + u * 8) * 2);
            const __half* src = (const __half*)g_Wh + (long)(k0 + k) * NDIM + u * 8;
            CP_ASYNC16(dst, src);
        }
        CP_COMMIT();
    };

    auto storeDiff = [&]() {
#pragma unroll
        for (int it = 0; it < 4; it++) {
            int idx = it * 256 + tid;
            int r = idx >> 4, c4 = idx & 15;
            __half2 p01 = __floats2half2_rn(ra[it].x - rp[it].x, ra[it].y - rp[it].y);
            __half2 p23 = __floats2half2_rn(ra[it].z - rp[it].z, ra[it].w - rp[it].w);
            __half2 q01 = __floats2half2_rn(ra[it].x - rn[it].x, ra[it].y - rn[it].y);
            __half2 q23 = __floats2half2_rn(ra[it].z - rn[it].z, ra[it].w - rn[it].w);
            *(uint2*)(&sdiff[r * KP + c4 * 4])        = make_uint2(h2u(p01), h2u(p23));
            *(uint2*)(&sdiff[(64 + r) * KP + c4 * 4]) = make_uint2(h2u(q01), h2u(q23));
        }
    };

    auto mmaK = [&](int kk, uint32_t wb) {
        const int kb = kk * 16;
        uint32_t A0[4], A1[4];
        LDSM4(A0[0], A0[1], A0[2], A0[3],
              a_base + (uint32_t)(((a_row) * KP + kb + a_kadd) * 2));
        LDSM4(A1[0], A1[1], A1[2], A1[3],
              a_base + (uint32_t)(((a_row + 16) * KP + kb + a_kadd) * 2));
#pragma unroll
        for (int nt = 0; nt < 4; nt++) {
            uint32_t B0, B1, B2, B3;
            LDSM4T(B0, B1, B2, B3,
                   wb + (uint32_t)(((kb + b_krow) * WP + b_ncol + nt * 16) * 2));
            MMA16816(acc[0][2 * nt],     A0[0], A0[1], A0[2], A0[3], B0, B1);
            MMA16816(acc[0][2 * nt + 1], A0[0], A0[1], A0[2], A0[3], B2, B3);
            MMA16816(acc[1][2 * nt],     A1[0], A1[1], A1[2], A1[3], B0, B1);
            MMA16816(acc[1][2 * nt + 1], A1[0], A1[1], A1[2], A1[3], B2, B3);
        }
    };

    // --- prologue: W(0) in flight, chunk-0 regs loading ---
    cpasyncW(0, w_base[0]);
    loadHalf(0, 0);
    loadHalf(0, 1);

    for (int t = 0; t < NCHUNK; t++) {
        const uint32_t wb = w_base[t & 1];
        const int kn = (t + 1 < NCHUNK) ? (t + 1) * KC : 0;   // wrap: harmless dummy

        __syncthreads();                          // MMA(t-1) done with sdiff & wbuf[(t-1)&1]
        cpasyncW(kn, w_base[(t + 1) & 1]);        // W(t+1) into the just-freed buffer
        storeDiff();                              // consumes chunk-t regs
        CP_WAIT1();                               // W(t) landed (W(t+1) may be pending)
        __syncthreads();                          // sdiff(t) + wbuf[t&1] visible

        loadHalf(kn, 0);                          // first half-burst of t+1
        mmaK(0, wb);
        mmaK(1, wb);
        loadHalf(kn, 1);                          // second half-burst, mid-MMA
        mmaK(2, wb);
        mmaK(3, wb);
    }

    // --- epilogue: per-row sum of squares ---
#pragma unroll
    for (int mt = 0; mt < 2; mt++) {
        float slo = 0.f, shi = 0.f;
#pragma unroll
        for (int j = 0; j < 8; j++) {
            slo += acc[mt][j][0] * acc[mt][j][0] + acc[mt][j][1] * acc[mt][j][1];
            shi += acc[mt][j][2] * acc[mt][j][2] + acc[mt][j][3] * acc[mt][j][3];
        }
        slo += __shfl_xor_sync(0xffffffffu, slo, 1);
        slo += __shfl_xor_sync(0xffffffffu, slo, 2);
        shi += __shfl_xor_sync(0xffffffffu, shi, 1);
        shi += __shfl_xor_sync(0xffffffffu, shi, 2);
        if ((lane & 3) == 0) {
            int r = mq * 32 + mt * 16 + (lane >> 2);
            sD[r][nh]     = slo;
            sD[r + 8][nh] = shi;
        }
    }
    __syncthreads();

    if (tid < 64) {
        float dp = sD[tid][0] + sD[tid][1];
        float dn = sD[tid + 64][0] + sD[tid + 64][1];
        float loss = dp - dn + ALPHA_C;
        loss = loss > 0.f ? loss : 0.f;
#pragma unroll
        for (int o = 16; o > 0; o >>= 1)
            loss += __shfl_xor_sync(0xffffffffu, loss, o);
        if (lane == 0) sRed[warp] = loss;
    }
    __syncthreads();

    // --- publish partial; last CTA reduces all (threadFenceReduction) ---
    if (tid == 0) {
        g_partial[blockIdx.x] = sRed[0] + sRed[1];
        __threadfence();
        unsigned ticket = atomicAdd(&g_ticket, 1u);
        sIsLast = (ticket == NCTA - 1);
    }
    __syncthreads();

    if (sIsLast) {
        if (tid < NCTA) {                         // NCTA = 128 -> warps 0-3
            float s = g_partial[tid];
#pragma unroll
            for (int o = 16; o > 0; o >>= 1)
                s += __shfl_xor_sync(0xffffffffu, s, o);
            if (lane == 0) sRed[warp] = s;
        }
        __syncthreads();
        if (tid == 0) {
            out[0] = (sRed[0] + sRed[1] + sRed[2] + sRed[3]) * (1.0f / (float)BTOT);
            g_ticket = 0;                         // reset for next graph replay
        }
    }
}

// ---------------------------------------------------------------------------
extern "C" void kernel_launch(void* const* d_in, const int* in_sizes, int n_in,
                              void* d_out, int out_size) {
    const float* A  = (const float*)d_in[0];  // batch_anchor
    const float* P  = (const float*)d_in[1];  // batch_pos
    const float* Ng = (const float*)d_in[2];  // batch_neg
    const float* W  = (const float*)d_in[3];  // W (b cancels)

    cudaFuncSetAttribute(triplet_main_kernel,
                         cudaFuncAttributeMaxDynamicSharedMemorySize,
                         DYN_SMEM_BYTES);

    convW_kernel<<<(KDIM * NDIM / 4) / 256, 256>>>(W);
    triplet_main_kernel<<<NCTA, 256, DYN_SMEM_BYTES>>>(A, P, Ng, (float*)d_out);
}

// round 15
// speedup vs baseline: 1.1122x; 1.1122x over previous
#include <cuda_runtime.h>
#include <cuda_fp16.h>
#include <cstdint>

// loss = mean(relu(||(a-p)W||^2 - ||(a-n)W||^2 + 0.2))   (bias b cancels)

#define ALPHA_C   0.2f
#define BTOT      8192
#define KDIM      2304
#define NDIM      128
#define ROWS_CTA  64
#define KC        128
#define KP        136         // diff row pitch (halves): 272B, conflict-free ldmatrix
#define WP        136         // W row pitch (halves): conflict-free ldmatrix.trans
#define NCHUNK    (KDIM / KC)       // 18
#define NCTA      (BTOT / ROWS_CTA) // 128
#define NTHR      512

#define DIFF_HALVES (128 * KP)      // 17408 (34816 B)
#define W_HALVES    (KC * WP)       // 17408 (34816 B per buffer)
#define DYN_SMEM_BYTES ((DIFF_HALVES + 2 * W_HALVES) * 2)   // 104448

__device__ __half   g_Wh[KDIM * NDIM];   // W fp16, native [k][n]
__device__ float    g_partial[NCTA];
__device__ unsigned g_ticket = 0;

static __device__ __forceinline__ uint32_t h2u(__half2 h) {
    return *reinterpret_cast<uint32_t*>(&h);
}

// ---------------------------------------------------------------------------
__global__ void convW_kernel(const float* __restrict__ W) {
    int gid = blockIdx.x * blockDim.x + threadIdx.x;     // one float4 each
    float4 v = ((const float4*)W)[gid];
    __half2* out = (__half2*)g_Wh;
    out[gid * 2]     = __floats2half2_rn(v.x, v.y);
    out[gid * 2 + 1] = __floats2half2_rn(v.z, v.w);
}

// ---------------------------------------------------------------------------
#define LDSM4(r0, r1, r2, r3, addr)                                          \
    asm volatile("ldmatrix.sync.aligned.m8n8.x4.shared.b16 {%0,%1,%2,%3}, [%4];" \
                 : "=r"(r0), "=r"(r1), "=r"(r2), "=r"(r3) : "r"(addr))

#define LDSM4T(r0, r1, r2, r3, addr)                                         \
    asm volatile("ldmatrix.sync.aligned.m8n8.x4.trans.shared.b16 {%0,%1,%2,%3}, [%4];" \
                 : "=r"(r0), "=r"(r1), "=r"(r2), "=r"(r3) : "r"(addr))

#define MMA16816(c, a0, a1, a2, a3, b0, b1)                                  \
    asm volatile("mma.sync.aligned.m16n8k16.row.col.f32.f16.f16.f32 "        \
                 "{%0,%1,%2,%3}, {%4,%5,%6,%7}, {%8,%9}, {%0,%1,%2,%3};"     \
                 : "+f"(c[0]), "+f"(c[1]), "+f"(c[2]), "+f"(c[3])            \
                 : "r"(a0), "r"(a1), "r"(a2), "r"(a3), "r"(b0), "r"(b1))

#define CP_ASYNC16(dst_u32, src_ptr)                                         \
    asm volatile("cp.async.cg.shared.global [%0], [%1], 16;"                 \
                 :: "r"(dst_u32), "l"(src_ptr))
#define CP_COMMIT()  asm volatile("cp.async.commit_group;")
#define CP_WAIT0()   asm volatile("cp.async.wait_group 0;")

__global__ void __launch_bounds__(NTHR, 1)
triplet_main_kernel(const float* __restrict__ A,
                    const float* __restrict__ P,
                    const float* __restrict__ Ng,
                    float* __restrict__ out) {
    extern __shared__ __align__(16) __half smem[];
    __half* sdiff = smem;                          // 128 x KP (dp rows 0-63, dn 64-127)
    __half* wbuf0 = smem + DIFF_HALVES;            // W double buffer
    __half* wbuf1 = wbuf0 + W_HALVES;
    __shared__ float sD[128][2];
    __shared__ float sRed[4];
    __shared__ int   sIsLast;

    const int tid  = threadIdx.x;
    const int warp = tid >> 5;
    const int lane = tid & 31;
    const int row0 = blockIdx.x * ROWS_CTA;

    const int mq = warp & 7;       // 16-row slice of the merged 128-row tile
    const int nh = warp >> 3;      // 64-col half

    const uint32_t a_base = (uint32_t)__cvta_generic_to_shared(sdiff);
    const uint32_t w_base[2] = { (uint32_t)__cvta_generic_to_shared(wbuf0),
                                 (uint32_t)__cvta_generic_to_shared(wbuf1) };

    // one-chunk register staging for A/P/N (48 regs)
    float4 ra[4], rp[4], rn[4];    // 64 rows x 128 floats / 512 thr = 4 float4 each

    float acc[8][4];               // 16 rows x 64 cols per warp
#pragma unroll
    for (int j = 0; j < 8; j++)
#pragma unroll
        for (int c = 0; c < 4; c++) acc[j][c] = 0.f;

    // ldmatrix per-lane address components
    const int a_row  = mq * 16 + (lane & 15);
    const int a_kadd = (lane >> 4) * 8;
    const int b_krow = (lane & 7) + ((lane >> 3) & 1) * 8;
    const int b_ncol = nh * 64 + (lane >> 4) * 8;

    auto loadRegs = [&](int k0) {
#pragma unroll
        for (int it = 0; it < 4; it++) {
            int idx = it * NTHR + tid;
            int r = idx >> 5, c4 = idx & 31;           // 32 float4 per 128-float row
            long off = (long)(row0 + r) * KDIM + k0 + c4 * 4;
            ra[it] = *(const float4*)(A + off);
            rp[it] = *(const float4*)(P + off);
            rn[it] = *(const float4*)(Ng + off);
        }
    };

    auto cpasyncW = [&](int k0, uint32_t wb) {
        // 128 k-rows x 128 halves = 2048 x 16B units; 4 per thread
#pragma unroll
        for (int it = 0; it < 4; it++) {
            int g = it * NTHR + tid;
            int k = g >> 4, u = g & 15;
            uint32_t dst = wb + (uint32_t)((k * WP + u * 8) * 2);
            const __half* src = (const __half*)g_Wh + (long)(k0 + k) * NDIM + u * 8;
            CP_ASYNC16(dst, src);
        }
        CP_COMMIT();
    };

    auto storeDiff = [&]() {
#pragma unroll
        for (int it = 0; it < 4; it++) {
            int idx = it * NTHR + tid;
            int r = idx >> 5, c4 = idx & 31;
            __half2 p01 = __floats2half2_rn(ra[it].x - rp[it].x, ra[it].y - rp[it].y);
            __half2 p23 = __floats2half2_rn(ra[it].z - rp[it].z, ra[it].w - rp[it].w);
            __half2 q01 = __floats2half2_rn(ra[it].x - rn[it].x, ra[it].y - rn[it].y);
            __half2 q23 = __floats2half2_rn(ra[it].z - rn[it].z, ra[it].w - rn[it].w);
            *(uint2*)(&sdiff[r * KP + c4 * 4])        = make_uint2(h2u(p01), h2u(p23));
            *(uint2*)(&sdiff[(64 + r) * KP + c4 * 4]) = make_uint2(h2u(q01), h2u(q23));
        }
    };

    // --- prologue: stage chunk 0 ---
    cpasyncW(0, w_base[0]);
    loadRegs(0);

    for (int t = 0; t < NCHUNK; t++) {
        const uint32_t wb = w_base[t & 1];

        __syncthreads();                          // MMA(t-1) done with sdiff & wbuf[(t-1)&1]
        storeDiff();                              // consumes chunk-t regs
        CP_WAIT0();                               // W(t) landed
        __syncthreads();                          // sdiff(t) + wbuf[t&1] visible

        if (t + 1 < NCHUNK) {
            cpasyncW((t + 1) * KC, w_base[(t + 1) & 1]);  // into free buffer
            loadRegs((t + 1) * KC);               // burst in flight under long MMA
        }

#pragma unroll
        for (int kk = 0; kk < KC / 16; kk++) {    // 8 k-steps
            const int kb = kk * 16;
            uint32_t A0[4];
            LDSM4(A0[0], A0[1], A0[2], A0[3],
                  a_base + (uint32_t)((a_row * KP + kb + a_kadd) * 2));
#pragma unroll
            for (int nt = 0; nt < 4; nt++) {
                uint32_t B0, B1, B2, B3;
                LDSM4T(B0, B1, B2, B3,
                       wb + (uint32_t)(((kb + b_krow) * WP + b_ncol + nt * 16) * 2));
                MMA16816(acc[2 * nt],     A0[0], A0[1], A0[2], A0[3], B0, B1);
                MMA16816(acc[2 * nt + 1], A0[0], A0[1], A0[2], A0[3], B2, B3);
            }
        }
    }

    // --- epilogue: per-row sum of squares ---
    {
        float slo = 0.f, shi = 0.f;
#pragma unroll
        for (int j = 0; j < 8; j++) {
            slo += acc[j][0] * acc[j][0] + acc[j][1] * acc[j][1];
            shi += acc[j][2] * acc[j][2] + acc[j][3] * acc[j][3];
        }
        slo += __shfl_xor_sync(0xffffffffu, slo, 1);
        slo += __shfl_xor_sync(0xffffffffu, slo, 2);
        shi += __shfl_xor_sync(0xffffffffu, shi, 1);
        shi += __shfl_xor_sync(0xffffffffu, shi, 2);
        if ((lane & 3) == 0) {
            int r = mq * 16 + (lane >> 2);
            sD[r][nh]     = slo;
            sD[r + 8][nh] = shi;
        }
    }
    __syncthreads();

    if (tid < 64) {
        float dp = sD[tid][0] + sD[tid][1];
        float dn = sD[tid + 64][0] + sD[tid + 64][1];
        float loss = dp - dn + ALPHA_C;
        loss = loss > 0.f ? loss : 0.f;
#pragma unroll
        for (int o = 16; o > 0; o >>= 1)
            loss += __shfl_xor_sync(0xffffffffu, loss, o);
        if (lane == 0) sRed[warp] = loss;
    }
    __syncthreads();

    // --- publish partial; last CTA reduces all (threadFenceReduction) ---
    if (tid == 0) {
        g_partial[blockIdx.x] = sRed[0] + sRed[1];
        __threadfence();
        unsigned ticket = atomicAdd(&g_ticket, 1u);
        sIsLast = (ticket == NCTA - 1);
    }
    __syncthreads();

    if (sIsLast) {
        if (tid < NCTA) {                         // NCTA = 128 -> warps 0-3
            float s = g_partial[tid];
#pragma unroll
            for (int o = 16; o > 0; o >>= 1)
                s += __shfl_xor_sync(0xffffffffu, s, o);
            if (lane == 0) sRed[warp] = s;
        }
        __syncthreads();
        if (tid == 0) {
            out[0] = (sRed[0] + sRed[1] + sRed[2] + sRed[3]) * (1.0f / (float)BTOT);
            g_ticket = 0;                         // reset for next graph replay
        }
    }
}

// ---------------------------------------------------------------------------
extern "C" void kernel_launch(void* const* d_in, const int* in_sizes, int n_in,
                              void* d_out, int out_size) {
    const float* A  = (const float*)d_in[0];  // batch_anchor
    const float* P  = (const float*)d_in[1];  // batch_pos
    const float* Ng = (const float*)d_in[2];  // batch_neg
    const float* W  = (const float*)d_in[3];  // W (b cancels)

    cudaFuncSetAttribute(triplet_main_kernel,
                         cudaFuncAttributeMaxDynamicSharedMemorySize,
                         DYN_SMEM_BYTES);

    convW_kernel<<<(KDIM * NDIM / 4) / 256, 256>>>(W);
    triplet_main_kernel<<<NCTA, NTHR, DYN_SMEM_BYTES>>>(A, P, Ng, (float*)d_out);
}